// round 13
// baseline (speedup 1.0000x reference)
#include <cuda_runtime.h>
#include <cuda_fp16.h>
#include <math.h>
#include <stdint.h>

#define BB     8192
#define OPTN   16
#define SHRD   22
#define UNIQN  8
#define OBSW   150
#define MROWS  131072

// ---------------- scratch (device globals) -----------------------------------
__device__ __half g_se_h[BB * 256];                 // 4 MB
__device__ __half g_ue_h[(size_t)MROWS * 128];      // 32 MB
__device__ __half g_t1h[(size_t)MROWS * 512];       // 128 MB
__device__ float  g_sec[(size_t)BB * 512];          // 16 MB: se @ tw1a^T
__device__ __half g_tw1ah[512 * 256];               // tw1[:, :256]  [n][k]
__device__ __half g_tw1bh[512 * 128];               // tw1[:, 256:]  [n][k]
__device__ __half g_tw2h[256 * 512];
__device__ __half g_uw2h[128 * 128];
__device__ float  g_pv[2 * MROWS];
__device__ float  g_pd[2 * MROWS];
__device__ int    g_flag[1024];
__device__ float  g_sw1t[22 * 256];
__device__ float  g_sw2t[256 * 256];
__device__ float  g_uw1t[8 * 128];

__device__ __forceinline__ void mma_f16(float* c, const uint32_t* a, const uint32_t* b) {
    asm volatile(
        "mma.sync.aligned.m16n8k16.row.col.f32.f16.f16.f32 "
        "{%0,%1,%2,%3}, {%4,%5,%6,%7}, {%8,%9}, {%0,%1,%2,%3};"
        : "+f"(c[0]), "+f"(c[1]), "+f"(c[2]), "+f"(c[3])
        : "r"(a[0]), "r"(a[1]), "r"(a[2]), "r"(a[3]), "r"(b[0]), "r"(b[1]));
}

__device__ __forceinline__ void ldmx4(uint32_t* r, uint32_t addr) {
    asm volatile("ldmatrix.sync.aligned.m8n8.x4.shared.b16 {%0,%1,%2,%3}, [%4];"
                 : "=r"(r[0]), "=r"(r[1]), "=r"(r[2]), "=r"(r[3]) : "r"(addr));
}

__device__ __forceinline__ void cpa16(uint32_t s, const void* g) {
    asm volatile("cp.async.cg.shared.global [%0], [%1], 16;" :: "r"(s), "l"(g));
}
#define CPA_COMMIT() asm volatile("cp.async.commit_group;" ::: "memory")
#define CPA_WAIT1()  asm volatile("cp.async.wait_group 1;"  ::: "memory")
#define CPA_WAIT0()  asm volatile("cp.async.wait_group 0;"  ::: "memory")
#define GDC_WAIT()   asm volatile("griddepcontrol.wait;" ::: "memory")
#define GDC_LAUNCH() asm volatile("griddepcontrol.launch_dependents;" ::: "memory")

// ---------------- prep -------------------------------------------------------
__global__ __launch_bounds__(256) void prep_kernel(
    const float* __restrict__ sw1, const float* __restrict__ sw2,
    const float* __restrict__ uw1, const float* __restrict__ uw2,
    const float* __restrict__ tw1, const float* __restrict__ tw2)
{
    int idx = blockIdx.x * 256 + threadIdx.x;
    if (idx < 512 * 384) {
        int n = idx / 384, k = idx - n * 384;
        __half v = __float2half(tw1[idx]);
        if (k < 256) g_tw1ah[n * 256 + k] = v;
        else         g_tw1bh[n * 128 + (k - 256)] = v;
    }
    if (idx < 256 * 512) g_tw2h[idx] = __float2half(tw2[idx]);
    if (idx < 128 * 128) g_uw2h[idx] = __float2half(uw2[idx]);
    if (idx < 256 * 256) { int o = idx / 256, k = idx - o * 256; g_sw2t[k * 256 + o] = sw2[idx]; }
    if (idx < 256 * 22)  { int o = idx / 22,  i = idx - o * 22;  g_sw1t[i * 256 + o] = sw1[idx]; }
    if (idx < 128 * 8)   { int o = idx / 8,   i = idx - o * 8;   g_uw1t[i * 128 + o] = uw1[idx]; }
    if (idx < 1024) g_flag[idx] = 0;
    GDC_LAUNCH();
}

// ---------------- shared-branch MLP (f32 math, fp16 out) ---------------------
__global__ __launch_bounds__(256) void se_kernel(
    const float* __restrict__ obs,
    const float* __restrict__ sb1, const float* __restrict__ sb2)
{
    __shared__ float xs[32][SHRD];
    __shared__ float h1[32][256];
    const int t = threadIdx.x;
    const int row0 = blockIdx.x * 32;

    for (int l = t; l < 32 * SHRD; l += 256) {
        int r = l / SHRD, c = l - r * SHRD;
        xs[r][c] = obs[(size_t)(row0 + r) * OBSW + c];
    }
    GDC_WAIT();
    __syncthreads();

    float acc[32];
#pragma unroll
    for (int r = 0; r < 32; ++r) acc[r] = 0.f;
    for (int i = 0; i < SHRD; ++i) {
        float wv = g_sw1t[i * 256 + t];
#pragma unroll
        for (int r = 0; r < 32; ++r) acc[r] += wv * xs[r][i];
    }
    float b1 = sb1[t];
#pragma unroll
    for (int r = 0; r < 32; ++r) h1[r][t] = fmaxf(acc[r] + b1, 0.f);
    __syncthreads();

#pragma unroll
    for (int r = 0; r < 32; ++r) acc[r] = 0.f;
    for (int k = 0; k < 256; ++k) {
        float wv = g_sw2t[k * 256 + t];
#pragma unroll
        for (int r = 0; r < 32; ++r) acc[r] += wv * h1[r][k];
    }
    float b2 = sb2[t];
#pragma unroll
    for (int r = 0; r < 32; ++r)
        g_se_h[(size_t)(row0 + r) * 256 + t] = __float2half(fmaxf(acc[r] + b2, 0.f));
    GDC_LAUNCH();
}

// ---------------- fused unique branch: obs -> h1 -> ue2 mma -> mask -> g_ue_h
__global__ __launch_bounds__(128) void ue_fused(
    const float* __restrict__ obs,
    const float* __restrict__ ub1, const float* __restrict__ ub2,
    const float* __restrict__ noop)
{
    constexpr int LDH = 40;
    constexpr int BUFH = 128 * LDH;

    extern __shared__ __align__(16) __half sm[];
    __half* As = sm;
    __half* Bs = sm + 4 * BUFH;
    __shared__ float xs[128][UNIQN];
    __shared__ float sbias[128];
    __shared__ float sne[128];

    const int tid  = threadIdx.x;
    const int lane = tid & 31;
    const int wid  = tid >> 5;
    const int wm   = (wid >> 1) * 64;
    const int wn   = (wid & 1) * 64;
    const int mB   = blockIdx.x * 128;
    const int gID  = lane >> 2;
    const int tIG  = lane & 3;
    const int q    = lane >> 3;
    const int r    = lane & 7;

    sbias[tid] = ub2[tid];
    sne[tid]   = noop[tid];

    const uint32_t AsB = (uint32_t)__cvta_generic_to_shared(As);
    const uint32_t BsB = (uint32_t)__cvta_generic_to_shared(Bs);

    GDC_WAIT();
    {
        const int arow = tid >> 2, kq4 = tid & 3;
#pragma unroll
        for (int it = 0; it < 4; ++it) {
            int k = it * 32 + kq4 * 8;
#pragma unroll
            for (int j = 0; j < 4; ++j) {
                int row = arow + 32 * j;
                cpa16(BsB + (it * BUFH + row * LDH + kq4 * 8) * 2,
                      g_uw2h + (size_t)row * 128 + k);
            }
        }
        CPA_COMMIT();
    }

    {
        int m = mB + tid;
        const float* p = obs + (size_t)(m >> 4) * OBSW + SHRD + (m & 15) * UNIQN;
#pragma unroll
        for (int i = 0; i < 4; ++i) {
            float2 v = *(const float2*)(p + 2 * i);
            xs[tid][2 * i]     = v.x;
            xs[tid][2 * i + 1] = v.y;
        }
    }
    __syncthreads();

    {
        const int c = tid;
        const int chunk = c >> 5, cc = c & 31;
        float w[UNIQN];
#pragma unroll
        for (int i = 0; i < UNIQN; ++i) w[i] = g_uw1t[i * 128 + c];
        float b1 = ub1[c];
#pragma unroll
        for (int pass = 0; pass < 4; ++pass) {
            float acc32[32];
#pragma unroll
            for (int rr = 0; rr < 32; ++rr) acc32[rr] = b1;
#pragma unroll
            for (int i = 0; i < UNIQN; ++i)
#pragma unroll
                for (int rr = 0; rr < 32; ++rr)
                    acc32[rr] += w[i] * xs[pass * 32 + rr][i];
#pragma unroll
            for (int rr = 0; rr < 32; ++rr)
                As[chunk * BUFH + (pass * 32 + rr) * LDH + cc] =
                    __float2half(fmaxf(acc32[rr], 0.f));
        }
    }
    CPA_WAIT0();
    __syncthreads();

    const uint32_t aOff = ((wm + ((q & 1) << 3) + r) * LDH + ((q >> 1) << 3)) * 2;
    const uint32_t bOff = ((wn + ((q >> 1) << 3) + r) * LDH + ((q & 1) << 3)) * 2;
    float acc[4][8][4] = {};
#pragma unroll
    for (int it = 0; it < 4; ++it) {
        const uint32_t aB = AsB + it * (BUFH * 2) + aOff;
        const uint32_t bB = BsB + it * (BUFH * 2) + bOff;
#pragma unroll
        for (int ks = 0; ks < 2; ++ks) {
            uint32_t af[4][4], bf[4][4];
#pragma unroll
            for (int mi = 0; mi < 4; ++mi)
                ldmx4(af[mi], aB + mi * (16 * LDH * 2) + ks * 32);
#pragma unroll
            for (int np = 0; np < 4; ++np)
                ldmx4(bf[np], bB + np * (16 * LDH * 2) + ks * 32);
#pragma unroll
            for (int mi = 0; mi < 4; ++mi)
#pragma unroll
                for (int ni = 0; ni < 8; ++ni)
                    mma_f16(acc[mi][ni], af[mi], &bf[ni >> 1][(ni & 1) * 2]);
        }
    }

    bool flg[4][2];
#pragma unroll
    for (int mi = 0; mi < 4; ++mi)
#pragma unroll
        for (int rh = 0; rh < 2; ++rh) {
            int lrow = wm + mi * 16 + rh * 8 + gID;
            flg[mi][rh] = (xs[lrow][0] == 1.0f);
        }
#pragma unroll
    for (int mi = 0; mi < 4; ++mi) {
#pragma unroll
        for (int ni = 0; ni < 8; ++ni) {
            int cl = wn + ni * 8 + 2 * tIG;
            float b0 = sbias[cl], b1 = sbias[cl + 1];
            float e0 = sne[cl], e1 = sne[cl + 1];
            int row = mB + wm + mi * 16 + gID;
            float v00 = flg[mi][0] ? e0 : fmaxf(acc[mi][ni][0] + b0, 0.f);
            float v01 = flg[mi][0] ? e1 : fmaxf(acc[mi][ni][1] + b1, 0.f);
            float v10 = flg[mi][1] ? e0 : fmaxf(acc[mi][ni][2] + b0, 0.f);
            float v11 = flg[mi][1] ? e1 : fmaxf(acc[mi][ni][3] + b1, 0.f);
            *(__half2*)(g_ue_h + (size_t)row * 128 + cl)       = __floats2half2_rn(v00, v01);
            *(__half2*)(g_ue_h + (size_t)(row + 8) * 128 + cl) = __floats2half2_rn(v10, v11);
        }
    }
    GDC_LAUNCH();
}

// ---------------- mma GEMMs, blk 128x128, 4 warps 64x64, 3-stage cp.async ----
// MODE 0 (SEC): A=g_se_h (M=8192, K=256), B=tw1a (N=512) -> f32 g_sec
// MODE 1 (T1):  A=g_ue_h (K=128), B=tw1b (N=512) -> +sec +bias relu -> g_t1h
// MODE 2 (T2):  A=g_t1h (K=512),  B=tw2 (N=256) -> partials + in-kernel combine
template <int MODE>
__global__ __launch_bounds__(128) void gemm_mma(
    const float* __restrict__ bias,
    const float* __restrict__ aux1,   // MODE2: vw
    const float* __restrict__ aux2,   // MODE2: dw
    const float* __restrict__ vb, const float* __restrict__ db,
    float* __restrict__ out)
{
    constexpr int KD  = (MODE == 0) ? 256 : (MODE == 1) ? 128 : 512;
    constexpr int LDH = 40;
    constexpr int BUFH = 128 * LDH;

    extern __shared__ __align__(16) __half sm[];
    __half* As = sm;                  // 3 * BUFH
    __half* Bs = sm + 3 * BUFH;       // 3 * BUFH
    __shared__ float sbias[128];
    __shared__ float sx1[128];
    __shared__ float sx2[128];
    __shared__ float stV[2][128];
    __shared__ float stD[2][128];
    __shared__ int s_old;

    const __half* __restrict__ Aw =
        (MODE == 0) ? g_se_h : (MODE == 1) ? g_ue_h : g_t1h;
    const __half* __restrict__ Bw =
        (MODE == 0) ? g_tw1ah : (MODE == 1) ? g_tw1bh : g_tw2h;

    const int tid  = threadIdx.x;
    const int lane = tid & 31;
    const int wid  = tid >> 5;
    const int wm   = (wid >> 1) * 64;
    const int wn   = (wid & 1) * 64;
    const int mB   = blockIdx.y * 128;
    const int nB   = blockIdx.x * 128;
    const int gID  = lane >> 2;
    const int tIG  = lane & 3;
    const int q    = lane >> 3;
    const int r    = lane & 7;

    if (MODE != 0) sbias[tid] = bias[nB + tid];
    if (MODE == 2) { sx1[tid] = aux1[nB + tid]; sx2[tid] = aux2[nB + tid]; }

    const uint32_t AsB = (uint32_t)__cvta_generic_to_shared(As);
    const uint32_t BsB = (uint32_t)__cvta_generic_to_shared(Bs);
    const uint32_t aOff = ((wm + ((q & 1) << 3) + r) * LDH + ((q >> 1) << 3)) * 2;
    const uint32_t bOff = ((wn + ((q >> 1) << 3) + r) * LDH + ((q & 1) << 3)) * 2;

    float acc[4][8][4] = {};

    const int arow = tid >> 2;        // 0..31
    const int kq4  = tid & 3;

    auto issue = [&](int it) {
        const int buf = it % 3;
        const int k = it * 32 + kq4 * 8;
#pragma unroll
        for (int j = 0; j < 4; ++j) {
            int row = arow + 32 * j;
            cpa16(AsB + (buf * BUFH + row * LDH + kq4 * 8) * 2,
                  Aw + (size_t)(mB + row) * KD + k);
            cpa16(BsB + (buf * BUFH + row * LDH + kq4 * 8) * 2,
                  Bw + (size_t)(nB + row) * KD + k);
        }
        CPA_COMMIT();
    };

    GDC_WAIT();
    constexpr int nIter = KD / 32;
    issue(0);
    issue(1);

    for (int it = 0; it < nIter; ++it) {
        if (it + 1 < nIter) CPA_WAIT1(); else CPA_WAIT0();
        __syncthreads();
        if (it + 2 < nIter) issue(it + 2);

        const int cur = it % 3;
        const uint32_t aB = AsB + cur * (BUFH * 2) + aOff;
        const uint32_t bB = BsB + cur * (BUFH * 2) + bOff;
#pragma unroll
        for (int ks = 0; ks < 2; ++ks) {
            uint32_t af[4][4], bf[4][4];
#pragma unroll
            for (int mi = 0; mi < 4; ++mi)
                ldmx4(af[mi], aB + mi * (16 * LDH * 2) + ks * 32);
#pragma unroll
            for (int np = 0; np < 4; ++np)
                ldmx4(bf[np], bB + np * (16 * LDH * 2) + ks * 32);
#pragma unroll
            for (int mi = 0; mi < 4; ++mi)
#pragma unroll
                for (int ni = 0; ni < 8; ++ni)
                    mma_f16(acc[mi][ni], af[mi], &bf[ni >> 1][(ni & 1) * 2]);
        }
    }

    if constexpr (MODE == 0) {
        // raw f32 partial (no bias/relu) -> g_sec
#pragma unroll
        for (int mi = 0; mi < 4; ++mi) {
#pragma unroll
            for (int ni = 0; ni < 8; ++ni) {
                int cl = wn + ni * 8 + 2 * tIG;
                int row = mB + wm + mi * 16 + gID;
                int col = nB + cl;
                *(float2*)(g_sec + (size_t)row * 512 + col) =
                    make_float2(acc[mi][ni][0], acc[mi][ni][1]);
                *(float2*)(g_sec + (size_t)(row + 8) * 512 + col) =
                    make_float2(acc[mi][ni][2], acc[mi][ni][3]);
            }
        }
    } else if constexpr (MODE == 1) {
#pragma unroll
        for (int mi = 0; mi < 4; ++mi) {
#pragma unroll
            for (int ni = 0; ni < 8; ++ni) {
                int cl = wn + ni * 8 + 2 * tIG;
                float b0 = sbias[cl], b1 = sbias[cl + 1];
                int row = mB + wm + mi * 16 + gID;
                int col = nB + cl;
                float2 s0 = *(const float2*)(g_sec + (size_t)(row >> 4) * 512 + col);
                float2 s1 = *(const float2*)(g_sec + (size_t)((row + 8) >> 4) * 512 + col);
                __half2 h0 = __floats2half2_rn(fmaxf(acc[mi][ni][0] + s0.x + b0, 0.f),
                                               fmaxf(acc[mi][ni][1] + s0.y + b1, 0.f));
                __half2 h1 = __floats2half2_rn(fmaxf(acc[mi][ni][2] + s1.x + b0, 0.f),
                                               fmaxf(acc[mi][ni][3] + s1.y + b1, 0.f));
                *(__half2*)(g_t1h + (size_t)row * 512 + col)       = h0;
                *(__half2*)(g_t1h + (size_t)(row + 8) * 512 + col) = h1;
            }
        }
    } else {
        float pv[8] = {}, pd[8] = {};
#pragma unroll
        for (int mi = 0; mi < 4; ++mi) {
#pragma unroll
            for (int ni = 0; ni < 8; ++ni) {
                int cl = wn + ni * 8 + 2 * tIG;
                float b0 = sbias[cl], b1 = sbias[cl + 1];
                float wv0 = sx1[cl], wv1 = sx1[cl + 1];
                float wd0 = sx2[cl], wd1 = sx2[cl + 1];
                float t0 = fmaxf(acc[mi][ni][0] + b0, 0.f);
                float t1 = fmaxf(acc[mi][ni][1] + b1, 0.f);
                float t2 = fmaxf(acc[mi][ni][2] + b0, 0.f);
                float t3 = fmaxf(acc[mi][ni][3] + b1, 0.f);
                pv[mi * 2]     += t0 * wv0 + t1 * wv1;
                pd[mi * 2]     += t0 * wd0 + t1 * wd1;
                pv[mi * 2 + 1] += t2 * wv0 + t3 * wv1;
                pd[mi * 2 + 1] += t2 * wd0 + t3 * wd1;
            }
        }
#pragma unroll
        for (int off = 1; off <= 2; off <<= 1) {
#pragma unroll
            for (int i = 0; i < 8; ++i) {
                pv[i] += __shfl_xor_sync(0xffffffffu, pv[i], off);
                pd[i] += __shfl_xor_sync(0xffffffffu, pd[i], off);
            }
        }
        if (tIG == 0) {
#pragma unroll
            for (int mi = 0; mi < 4; ++mi)
#pragma unroll
                for (int rh = 0; rh < 2; ++rh) {
                    int row = wm + mi * 16 + rh * 8 + gID;
                    stV[wid & 1][row] = pv[mi * 2 + rh];
                    stD[wid & 1][row] = pd[mi * 2 + rh];
                }
        }
        __syncthreads();
        {
            float v = stV[0][tid] + stV[1][tid];
            float d = stD[0][tid] + stD[1][tid];
            size_t o = (size_t)blockIdx.x * MROWS + mB + tid;
            g_pv[o] = v;
            g_pd[o] = d;
        }
        __threadfence();
        __syncthreads();
        if (tid == 0) s_old = atomicAdd(&g_flag[blockIdx.y], 1);
        __syncthreads();
        if (s_old == 1) {
            __threadfence();
            int mm = mB + tid;
            float v = g_pv[mm] + g_pv[MROWS + mm] + vb[0];
            float s = g_pd[mm] + g_pd[MROWS + mm] + db[0];
            out[mm] = v;
            out[MROWS + mm] = 1.f / (1.f + expf(-s)) * 0.4f + 0.1f;
        }
    }
    GDC_LAUNCH();
}

// ---------------- launch -----------------------------------------------------
extern "C" void kernel_launch(void* const* d_in, const int* in_sizes, int n_in,
                              void* d_out, int out_size)
{
    (void)in_sizes; (void)n_in; (void)out_size;
    const float* obs  = (const float*)d_in[0];
    const float* sw1  = (const float*)d_in[1];
    const float* sb1  = (const float*)d_in[2];
    const float* sw2  = (const float*)d_in[3];
    const float* sb2  = (const float*)d_in[4];
    const float* uw1  = (const float*)d_in[5];
    const float* ub1  = (const float*)d_in[6];
    const float* uw2  = (const float*)d_in[7];
    const float* ub2  = (const float*)d_in[8];
    const float* noop = (const float*)d_in[9];
    const float* tw1  = (const float*)d_in[10];
    const float* tb1  = (const float*)d_in[11];
    const float* tw2  = (const float*)d_in[12];
    const float* tb2  = (const float*)d_in[13];
    const float* vw   = (const float*)d_in[14];
    const float* vb   = (const float*)d_in[15];
    const float* dw   = (const float*)d_in[16];
    const float* db   = (const float*)d_in[17];
    float* out = (float*)d_out;

    const int smemG = 6 * 128 * 40 * 2;   // 61440 B
    const int smemU = 8 * 128 * 40 * 2;   // 81920 B
    static bool attr_done = false;
    if (!attr_done) {
        cudaFuncSetAttribute(ue_fused,    cudaFuncAttributeMaxDynamicSharedMemorySize, smemU);
        cudaFuncSetAttribute(gemm_mma<0>, cudaFuncAttributeMaxDynamicSharedMemorySize, smemG);
        cudaFuncSetAttribute(gemm_mma<1>, cudaFuncAttributeMaxDynamicSharedMemorySize, smemG);
        cudaFuncSetAttribute(gemm_mma<2>, cudaFuncAttributeMaxDynamicSharedMemorySize, smemG);
        attr_done = true;
    }

    cudaLaunchAttribute at[1];
    at[0].id = cudaLaunchAttributeProgrammaticStreamSerialization;
    at[0].val.programmaticStreamSerializationAllowed = 1;

    auto mkcfg = [&](dim3 g, dim3 b, int smem) {
        cudaLaunchConfig_t c = {};
        c.gridDim = g; c.blockDim = b; c.dynamicSmemBytes = (size_t)smem;
        c.stream = 0; c.attrs = at; c.numAttrs = 1;
        return c;
    };

    {
        cudaLaunchConfig_t c = mkcfg(dim3(768), dim3(256), 0);
        cudaLaunchKernelEx(&c, prep_kernel, sw1, sw2, uw1, uw2, tw1, tw2);
    }
    {
        cudaLaunchConfig_t c = mkcfg(dim3(BB / 32), dim3(256), 0);
        cudaLaunchKernelEx(&c, se_kernel, obs, sb1, sb2);
    }
    {   // sec = se @ tw1a^T   (M=8192)
        cudaLaunchConfig_t c = mkcfg(dim3(4, BB / 128), dim3(128), smemG);
        cudaLaunchKernelEx(&c, gemm_mma<0>, (const float*)nullptr,
                           (const float*)nullptr, (const float*)nullptr,
                           (const float*)nullptr, (const float*)nullptr,
                           (float*)nullptr);
    }
    {
        cudaLaunchConfig_t c = mkcfg(dim3(MROWS / 128), dim3(128), smemU);
        cudaLaunchKernelEx(&c, ue_fused, obs, ub1, ub2, noop);
    }
    {   // t1 = relu(ue @ tw1b^T + sec + tb1)
        cudaLaunchConfig_t c = mkcfg(dim3(4, MROWS / 128), dim3(128), smemG);
        cudaLaunchKernelEx(&c, gemm_mma<1>, tb1, (const float*)nullptr,
                           (const float*)nullptr, (const float*)nullptr,
                           (const float*)nullptr, (float*)nullptr);
    }
    {
        cudaLaunchConfig_t c = mkcfg(dim3(2, MROWS / 128), dim3(128), smemG);
        cudaLaunchKernelEx(&c, gemm_mma<2>, tb2, vw, dw, vb, db, out);
    }
}

// round 14
// speedup vs baseline: 1.3209x; 1.3209x over previous
#include <cuda_runtime.h>
#include <cuda_fp16.h>
#include <math.h>
#include <stdint.h>

#define BB     8192
#define OPTN   16
#define SHRD   22
#define UNIQN  8
#define OBSW   150
#define MROWS  131072

// ---------------- scratch (device globals) -----------------------------------
__device__ __half g_se_h[BB * 256];                 // 4 MB
__device__ __half g_ue_h[(size_t)MROWS * 128];      // 32 MB
__device__ float  g_sec[(size_t)BB * 512];          // 16 MB: se @ tw1a^T
__device__ __half g_tw1ah[512 * 256];               // tw1[:, :256]  [n][k]
__device__ __half g_tw1bh[512 * 128];               // tw1[:, 256:]  [n][k]
__device__ __half g_tw2h[256 * 512];
__device__ __half g_uw2h[128 * 128];
__device__ float  g_sw1t[22 * 256];
__device__ float  g_sw2t[256 * 256];
__device__ float  g_uw1t[8 * 128];

__device__ __forceinline__ void mma_f16(float* c, const uint32_t* a, const uint32_t* b) {
    asm volatile(
        "mma.sync.aligned.m16n8k16.row.col.f32.f16.f16.f32 "
        "{%0,%1,%2,%3}, {%4,%5,%6,%7}, {%8,%9}, {%0,%1,%2,%3};"
        : "+f"(c[0]), "+f"(c[1]), "+f"(c[2]), "+f"(c[3])
        : "r"(a[0]), "r"(a[1]), "r"(a[2]), "r"(a[3]), "r"(b[0]), "r"(b[1]));
}

__device__ __forceinline__ void ldmx4(uint32_t* r, uint32_t addr) {
    asm volatile("ldmatrix.sync.aligned.m8n8.x4.shared.b16 {%0,%1,%2,%3}, [%4];"
                 : "=r"(r[0]), "=r"(r[1]), "=r"(r[2]), "=r"(r[3]) : "r"(addr));
}

__device__ __forceinline__ void cpa16(uint32_t s, const void* g) {
    asm volatile("cp.async.cg.shared.global [%0], [%1], 16;" :: "r"(s), "l"(g));
}
#define CPA_COMMIT() asm volatile("cp.async.commit_group;" ::: "memory")
#define CPA_WAIT1()  asm volatile("cp.async.wait_group 1;"  ::: "memory")
#define CPA_WAIT0()  asm volatile("cp.async.wait_group 0;"  ::: "memory")
#define GDC_WAIT()   asm volatile("griddepcontrol.wait;" ::: "memory")
#define GDC_LAUNCH() asm volatile("griddepcontrol.launch_dependents;" ::: "memory")

// ---------------- prep -------------------------------------------------------
__global__ __launch_bounds__(256) void prep_kernel(
    const float* __restrict__ sw1, const float* __restrict__ sw2,
    const float* __restrict__ uw1, const float* __restrict__ uw2,
    const float* __restrict__ tw1, const float* __restrict__ tw2)
{
    int idx = blockIdx.x * 256 + threadIdx.x;
    if (idx < 512 * 384) {
        int n = idx / 384, k = idx - n * 384;
        __half v = __float2half(tw1[idx]);
        if (k < 256) g_tw1ah[n * 256 + k] = v;
        else         g_tw1bh[n * 128 + (k - 256)] = v;
    }
    if (idx < 256 * 512) g_tw2h[idx] = __float2half(tw2[idx]);
    if (idx < 128 * 128) g_uw2h[idx] = __float2half(uw2[idx]);
    if (idx < 256 * 256) { int o = idx / 256, k = idx - o * 256; g_sw2t[k * 256 + o] = sw2[idx]; }
    if (idx < 256 * 22)  { int o = idx / 22,  i = idx - o * 22;  g_sw1t[i * 256 + o] = sw1[idx]; }
    if (idx < 128 * 8)   { int o = idx / 8,   i = idx - o * 8;   g_uw1t[i * 128 + o] = uw1[idx]; }
    GDC_LAUNCH();
}

// ---------------- shared-branch MLP (f32 math, fp16 out) ---------------------
__global__ __launch_bounds__(256) void se_kernel(
    const float* __restrict__ obs,
    const float* __restrict__ sb1, const float* __restrict__ sb2)
{
    __shared__ float xs[32][SHRD];
    __shared__ float h1[32][256];
    const int t = threadIdx.x;
    const int row0 = blockIdx.x * 32;

    for (int l = t; l < 32 * SHRD; l += 256) {
        int r = l / SHRD, c = l - r * SHRD;
        xs[r][c] = obs[(size_t)(row0 + r) * OBSW + c];
    }
    GDC_WAIT();
    __syncthreads();

    float acc[32];
#pragma unroll
    for (int r = 0; r < 32; ++r) acc[r] = 0.f;
    for (int i = 0; i < SHRD; ++i) {
        float wv = g_sw1t[i * 256 + t];
#pragma unroll
        for (int r = 0; r < 32; ++r) acc[r] += wv * xs[r][i];
    }
    float b1 = sb1[t];
#pragma unroll
    for (int r = 0; r < 32; ++r) h1[r][t] = fmaxf(acc[r] + b1, 0.f);
    __syncthreads();

#pragma unroll
    for (int r = 0; r < 32; ++r) acc[r] = 0.f;
    for (int k = 0; k < 256; ++k) {
        float wv = g_sw2t[k * 256 + t];
#pragma unroll
        for (int r = 0; r < 32; ++r) acc[r] += wv * h1[r][k];
    }
    float b2 = sb2[t];
#pragma unroll
    for (int r = 0; r < 32; ++r)
        g_se_h[(size_t)(row0 + r) * 256 + t] = __float2half(fmaxf(acc[r] + b2, 0.f));
    GDC_LAUNCH();
}

// ---------------- sec = se @ tw1a^T (M=8192, K=256, N=512), raw f32 ----------
__global__ __launch_bounds__(128) void sec_gemm()
{
    constexpr int KD  = 256;
    constexpr int LDH = 40;
    constexpr int BUFH = 128 * LDH;

    extern __shared__ __align__(16) __half sm[];
    __half* As = sm;
    __half* Bs = sm + 3 * BUFH;

    const int tid  = threadIdx.x;
    const int lane = tid & 31;
    const int wid  = tid >> 5;
    const int wm   = (wid >> 1) * 64;
    const int wn   = (wid & 1) * 64;
    const int mB   = blockIdx.y * 128;
    const int nB   = blockIdx.x * 128;
    const int gID  = lane >> 2;
    const int tIG  = lane & 3;
    const int q    = lane >> 3;
    const int r    = lane & 7;

    const uint32_t AsB = (uint32_t)__cvta_generic_to_shared(As);
    const uint32_t BsB = (uint32_t)__cvta_generic_to_shared(Bs);
    const uint32_t aOff = ((wm + ((q & 1) << 3) + r) * LDH + ((q >> 1) << 3)) * 2;
    const uint32_t bOff = ((wn + ((q >> 1) << 3) + r) * LDH + ((q & 1) << 3)) * 2;

    float acc[4][8][4] = {};
    const int arow = tid >> 2, kq4 = tid & 3;

    auto issue = [&](int it) {
        const int buf = it % 3;
        const int k = it * 32 + kq4 * 8;
#pragma unroll
        for (int j = 0; j < 4; ++j) {
            int row = arow + 32 * j;
            cpa16(AsB + (buf * BUFH + row * LDH + kq4 * 8) * 2,
                  g_se_h + (size_t)(mB + row) * 256 + k);
            cpa16(BsB + (buf * BUFH + row * LDH + kq4 * 8) * 2,
                  g_tw1ah + (size_t)(nB + row) * 256 + k);
        }
        CPA_COMMIT();
    };

    GDC_WAIT();
    issue(0);
    issue(1);
    for (int it = 0; it < 8; ++it) {
        if (it + 1 < 8) CPA_WAIT1(); else CPA_WAIT0();
        __syncthreads();
        if (it + 2 < 8) issue(it + 2);
        const int cur = it % 3;
        const uint32_t aB = AsB + cur * (BUFH * 2) + aOff;
        const uint32_t bB = BsB + cur * (BUFH * 2) + bOff;
#pragma unroll
        for (int ks = 0; ks < 2; ++ks) {
            uint32_t af[4][4], bf[4][4];
#pragma unroll
            for (int mi = 0; mi < 4; ++mi)
                ldmx4(af[mi], aB + mi * (16 * LDH * 2) + ks * 32);
#pragma unroll
            for (int np = 0; np < 4; ++np)
                ldmx4(bf[np], bB + np * (16 * LDH * 2) + ks * 32);
#pragma unroll
            for (int mi = 0; mi < 4; ++mi)
#pragma unroll
                for (int ni = 0; ni < 8; ++ni)
                    mma_f16(acc[mi][ni], af[mi], &bf[ni >> 1][(ni & 1) * 2]);
        }
    }
#pragma unroll
    for (int mi = 0; mi < 4; ++mi) {
#pragma unroll
        for (int ni = 0; ni < 8; ++ni) {
            int cl = wn + ni * 8 + 2 * tIG;
            int row = mB + wm + mi * 16 + gID;
            int col = nB + cl;
            *(float2*)(g_sec + (size_t)row * 512 + col) =
                make_float2(acc[mi][ni][0], acc[mi][ni][1]);
            *(float2*)(g_sec + (size_t)(row + 8) * 512 + col) =
                make_float2(acc[mi][ni][2], acc[mi][ni][3]);
        }
    }
    GDC_LAUNCH();
}

// ---------------- fused unique branch: obs -> h1 -> ue2 mma -> mask -> g_ue_h
__global__ __launch_bounds__(128) void ue_fused(
    const float* __restrict__ obs,
    const float* __restrict__ ub1, const float* __restrict__ ub2,
    const float* __restrict__ noop)
{
    constexpr int LDH = 40;
    constexpr int BUFH = 128 * LDH;

    extern __shared__ __align__(16) __half sm[];
    __half* As = sm;
    __half* Bs = sm + 4 * BUFH;
    __shared__ float xs[128][UNIQN];
    __shared__ float sbias[128];
    __shared__ float sne[128];

    const int tid  = threadIdx.x;
    const int lane = tid & 31;
    const int wid  = tid >> 5;
    const int wm   = (wid >> 1) * 64;
    const int wn   = (wid & 1) * 64;
    const int mB   = blockIdx.x * 128;
    const int gID  = lane >> 2;
    const int tIG  = lane & 3;
    const int q    = lane >> 3;
    const int r    = lane & 7;

    sbias[tid] = ub2[tid];
    sne[tid]   = noop[tid];

    const uint32_t AsB = (uint32_t)__cvta_generic_to_shared(As);
    const uint32_t BsB = (uint32_t)__cvta_generic_to_shared(Bs);

    GDC_WAIT();
    {
        const int arow = tid >> 2, kq4 = tid & 3;
#pragma unroll
        for (int it = 0; it < 4; ++it) {
            int k = it * 32 + kq4 * 8;
#pragma unroll
            for (int j = 0; j < 4; ++j) {
                int row = arow + 32 * j;
                cpa16(BsB + (it * BUFH + row * LDH + kq4 * 8) * 2,
                      g_uw2h + (size_t)row * 128 + k);
            }
        }
        CPA_COMMIT();
    }

    {
        int m = mB + tid;
        const float* p = obs + (size_t)(m >> 4) * OBSW + SHRD + (m & 15) * UNIQN;
#pragma unroll
        for (int i = 0; i < 4; ++i) {
            float2 v = *(const float2*)(p + 2 * i);
            xs[tid][2 * i]     = v.x;
            xs[tid][2 * i + 1] = v.y;
        }
    }
    __syncthreads();

    {
        const int c = tid;
        const int chunk = c >> 5, cc = c & 31;
        float w[UNIQN];
#pragma unroll
        for (int i = 0; i < UNIQN; ++i) w[i] = g_uw1t[i * 128 + c];
        float b1 = ub1[c];
#pragma unroll
        for (int pass = 0; pass < 4; ++pass) {
            float acc32[32];
#pragma unroll
            for (int rr = 0; rr < 32; ++rr) acc32[rr] = b1;
#pragma unroll
            for (int i = 0; i < UNIQN; ++i)
#pragma unroll
                for (int rr = 0; rr < 32; ++rr)
                    acc32[rr] += w[i] * xs[pass * 32 + rr][i];
#pragma unroll
            for (int rr = 0; rr < 32; ++rr)
                As[chunk * BUFH + (pass * 32 + rr) * LDH + cc] =
                    __float2half(fmaxf(acc32[rr], 0.f));
        }
    }
    CPA_WAIT0();
    __syncthreads();

    const uint32_t aOff = ((wm + ((q & 1) << 3) + r) * LDH + ((q >> 1) << 3)) * 2;
    const uint32_t bOff = ((wn + ((q >> 1) << 3) + r) * LDH + ((q & 1) << 3)) * 2;
    float acc[4][8][4] = {};
#pragma unroll
    for (int it = 0; it < 4; ++it) {
        const uint32_t aB = AsB + it * (BUFH * 2) + aOff;
        const uint32_t bB = BsB + it * (BUFH * 2) + bOff;
#pragma unroll
        for (int ks = 0; ks < 2; ++ks) {
            uint32_t af[4][4], bf[4][4];
#pragma unroll
            for (int mi = 0; mi < 4; ++mi)
                ldmx4(af[mi], aB + mi * (16 * LDH * 2) + ks * 32);
#pragma unroll
            for (int np = 0; np < 4; ++np)
                ldmx4(bf[np], bB + np * (16 * LDH * 2) + ks * 32);
#pragma unroll
            for (int mi = 0; mi < 4; ++mi)
#pragma unroll
                for (int ni = 0; ni < 8; ++ni)
                    mma_f16(acc[mi][ni], af[mi], &bf[ni >> 1][(ni & 1) * 2]);
        }
    }

    bool flg[4][2];
#pragma unroll
    for (int mi = 0; mi < 4; ++mi)
#pragma unroll
        for (int rh = 0; rh < 2; ++rh) {
            int lrow = wm + mi * 16 + rh * 8 + gID;
            flg[mi][rh] = (xs[lrow][0] == 1.0f);
        }
#pragma unroll
    for (int mi = 0; mi < 4; ++mi) {
#pragma unroll
        for (int ni = 0; ni < 8; ++ni) {
            int cl = wn + ni * 8 + 2 * tIG;
            float b0 = sbias[cl], b1 = sbias[cl + 1];
            float e0 = sne[cl], e1 = sne[cl + 1];
            int row = mB + wm + mi * 16 + gID;
            float v00 = flg[mi][0] ? e0 : fmaxf(acc[mi][ni][0] + b0, 0.f);
            float v01 = flg[mi][0] ? e1 : fmaxf(acc[mi][ni][1] + b1, 0.f);
            float v10 = flg[mi][1] ? e0 : fmaxf(acc[mi][ni][2] + b0, 0.f);
            float v11 = flg[mi][1] ? e1 : fmaxf(acc[mi][ni][3] + b1, 0.f);
            *(__half2*)(g_ue_h + (size_t)row * 128 + cl)       = __floats2half2_rn(v00, v01);
            *(__half2*)(g_ue_h + (size_t)(row + 8) * 128 + cl) = __floats2half2_rn(v10, v11);
        }
    }
    GDC_LAUNCH();
}

// ---------------- mega trunk: ue(resident) -> t1(smem) -> t2 -> heads -> out -
// 256 threads, 8 warps (2m x 4n of 64x64). One CTA = 128 rows.
// Smem: T1 16 chunks (160KB; chunks 8-11 double as the resident-A region
// during phase 1) + B pipe 3 x 20KB = 220KB.
__global__ __launch_bounds__(256) void mega_trunk(
    const float* __restrict__ tb1, const float* __restrict__ tb2,
    const float* __restrict__ vw,  const float* __restrict__ dw,
    const float* __restrict__ vb,  const float* __restrict__ db,
    float* __restrict__ out)
{
    constexpr int LDH = 40;
    constexpr int CH  = 128 * LDH;      // 5120 halfs
    constexpr int BCH = 256 * LDH;      // 10240 halfs

    extern __shared__ __align__(16) __half sm[];
    __half* T1 = sm;                    // 16 * CH
    __half* AR = sm + 8 * CH;           // resident ue, aliases T1 chunks 8..11
    __half* Bp = sm + 16 * CH;          // 3 * BCH
    __shared__ float sb1f[512];
    __shared__ float sb2[256], svw[256], sdw[256];

    const int tid  = threadIdx.x;
    const int lane = tid & 31;
    const int wid  = tid >> 5;
    const int wm   = (wid >> 2) * 64;
    const int wn   = (wid & 3) * 64;
    const int mB   = blockIdx.x * 128;
    const int gID  = lane >> 2;
    const int tIG  = lane & 3;
    const int q    = lane >> 3;
    const int r    = lane & 7;

    sb1f[tid] = tb1[tid];
    sb1f[256 + tid] = tb1[256 + tid];
    sb2[tid] = tb2[tid];
    svw[tid] = vw[tid];
    sdw[tid] = dw[tid];

    const uint32_t T1B = (uint32_t)__cvta_generic_to_shared(T1);
    const uint32_t ARB = (uint32_t)__cvta_generic_to_shared(AR);
    const uint32_t BpB = (uint32_t)__cvta_generic_to_shared(Bp);
    const uint32_t aOff = ((wm + ((q & 1) << 3) + r) * LDH + ((q >> 1) << 3)) * 2;
    const uint32_t bOff = ((wn + ((q >> 1) << 3) + r) * LDH + ((q & 1) << 3)) * 2;

    const int arow = tid >> 2;          // 0..63
    const int kq4  = tid & 3;

    float acc[4][8][4];

    GDC_WAIT();
    // preload resident A = ue tile [128,128] into AR (4 chunks) -- one group
    {
#pragma unroll
        for (int c = 0; c < 4; ++c) {
            int k = c * 32 + kq4 * 8;
#pragma unroll
            for (int j = 0; j < 2; ++j) {
                int row = arow + 64 * j;
                cpa16(ARB + (c * CH + row * LDH + kq4 * 8) * 2,
                      g_ue_h + (size_t)(mB + row) * 128 + k);
            }
        }
        CPA_COMMIT();
    }

    // ---------------- phase 1: t1 = relu(ue @ tw1b^T + sec + tb1), 2 halves --
    auto issueB1 = [&](int i) {       // i in [0,8): h = i>>2, kc = i&3
        const int buf = i % 3;
        const int k = (i & 3) * 32 + kq4 * 8;
        const int nbase = (i >> 2) * 256;
#pragma unroll
        for (int j = 0; j < 4; ++j) {
            int row = arow + 64 * j;
            cpa16(BpB + (buf * BCH + row * LDH + kq4 * 8) * 2,
                  g_tw1bh + (size_t)(nbase + row) * 128 + k);
        }
        CPA_COMMIT();
    };

    issueB1(0);
    issueB1(1);
    for (int h = 0; h < 2; ++h) {
#pragma unroll
        for (int mi = 0; mi < 4; ++mi)
#pragma unroll
            for (int ni = 0; ni < 8; ++ni)
#pragma unroll
                for (int c = 0; c < 4; ++c) acc[mi][ni][c] = 0.f;

        for (int kc = 0; kc < 4; ++kc) {
            const int i = h * 4 + kc;
            if (i < 7) CPA_WAIT1(); else CPA_WAIT0();
            __syncthreads();
            if (i + 2 < 8) issueB1(i + 2);
            const uint32_t aB = ARB + kc * (CH * 2) + aOff;
            const uint32_t bB = BpB + (i % 3) * (BCH * 2) + bOff;
#pragma unroll
            for (int ks = 0; ks < 2; ++ks) {
                uint32_t af[4][4], bf[4][4];
#pragma unroll
                for (int mi = 0; mi < 4; ++mi)
                    ldmx4(af[mi], aB + mi * (16 * LDH * 2) + ks * 32);
#pragma unroll
                for (int np = 0; np < 4; ++np)
                    ldmx4(bf[np], bB + np * (16 * LDH * 2) + ks * 32);
#pragma unroll
                for (int mi = 0; mi < 4; ++mi)
#pragma unroll
                    for (int ni = 0; ni < 8; ++ni)
                        mma_f16(acc[mi][ni], af[mi], &bf[ni >> 1][(ni & 1) * 2]);
            }
        }
        // all warps done reading AR / buffers before epilogue overwrites T1
        __syncthreads();

        // epilogue: + sec + bias, relu -> fp16 -> T1 chunks [h*8, h*8+8)
        // (h=1 writes chunks 8-15 which include AR -- safe: AR is dead now)
#pragma unroll
        for (int mi = 0; mi < 4; ++mi) {
#pragma unroll
            for (int ni = 0; ni < 8; ++ni) {
                int coll = wn + ni * 8 + 2 * tIG;
                int colg = h * 256 + coll;
                float b0 = sb1f[colg], b1 = sb1f[colg + 1];
                int chunk = colg >> 5;
                int cm = coll & 31;
                int row = wm + mi * 16 + gID;
                float2 s0 = *(const float2*)(g_sec + (size_t)((mB + row) >> 4) * 512 + colg);
                float2 s1 = *(const float2*)(g_sec + (size_t)((mB + row + 8) >> 4) * 512 + colg);
                __half2 h0 = __floats2half2_rn(fmaxf(acc[mi][ni][0] + s0.x + b0, 0.f),
                                               fmaxf(acc[mi][ni][1] + s0.y + b1, 0.f));
                __half2 h1 = __floats2half2_rn(fmaxf(acc[mi][ni][2] + s1.x + b0, 0.f),
                                               fmaxf(acc[mi][ni][3] + s1.y + b1, 0.f));
                *(__half2*)(T1 + chunk * CH + row * LDH + cm)       = h0;
                *(__half2*)(T1 + chunk * CH + (row + 8) * LDH + cm) = h1;
            }
        }
        __syncthreads();
    }

    // ---------------- phase 2: t2 = relu(t1 @ tw2^T + tb2) + heads -----------
#pragma unroll
    for (int mi = 0; mi < 4; ++mi)
#pragma unroll
        for (int ni = 0; ni < 8; ++ni)
#pragma unroll
            for (int c = 0; c < 4; ++c) acc[mi][ni][c] = 0.f;

    auto issue2 = [&](int it) {
        const int buf = it % 3;
        const int k = it * 32 + kq4 * 8;
#pragma unroll
        for (int j = 0; j < 4; ++j) {
            int row = arow + 64 * j;
            cpa16(BpB + (buf * BCH + row * LDH + kq4 * 8) * 2,
                  g_tw2h + (size_t)row * 512 + k);
        }
        CPA_COMMIT();
    };

    issue2(0);
    issue2(1);
    for (int it = 0; it < 16; ++it) {
        if (it < 15) CPA_WAIT1(); else CPA_WAIT0();
        __syncthreads();
        if (it + 2 < 16) issue2(it + 2);
        const uint32_t aB = T1B + it * (CH * 2) + aOff;
        const uint32_t bB = BpB + (it % 3) * (BCH * 2) + bOff;
#pragma unroll
        for (int ks = 0; ks < 2; ++ks) {
            uint32_t af[4][4], bf[4][4];
#pragma unroll
            for (int mi = 0; mi < 4; ++mi)
                ldmx4(af[mi], aB + mi * (16 * LDH * 2) + ks * 32);
#pragma unroll
            for (int np = 0; np < 4; ++np)
                ldmx4(bf[np], bB + np * (16 * LDH * 2) + ks * 32);
#pragma unroll
            for (int mi = 0; mi < 4; ++mi)
#pragma unroll
                for (int ni = 0; ni < 8; ++ni)
                    mma_f16(acc[mi][ni], af[mi], &bf[ni >> 1][(ni & 1) * 2]);
        }
    }

    // heads over full N=256 -> final outputs
    float pv[8] = {}, pd[8] = {};
#pragma unroll
    for (int mi = 0; mi < 4; ++mi) {
#pragma unroll
        for (int ni = 0; ni < 8; ++ni) {
            int cl = wn + ni * 8 + 2 * tIG;
            float b0 = sb2[cl], b1 = sb2[cl + 1];
            float wv0 = svw[cl], wv1 = svw[cl + 1];
            float wd0 = sdw[cl], wd1 = sdw[cl + 1];
            float t0 = fmaxf(acc[mi][ni][0] + b0, 0.f);
            float t1 = fmaxf(acc[mi][ni][1] + b1, 0.f);
            float t2 = fmaxf(acc[mi][ni][2] + b0, 0.f);
            float t3 = fmaxf(acc[mi][ni][3] + b1, 0.f);
            pv[mi * 2]     += t0 * wv0 + t1 * wv1;
            pd[mi * 2]     += t0 * wd0 + t1 * wd1;
            pv[mi * 2 + 1] += t2 * wv0 + t3 * wv1;
            pd[mi * 2 + 1] += t2 * wd0 + t3 * wd1;
        }
    }
#pragma unroll
    for (int off = 1; off <= 2; off <<= 1) {
#pragma unroll
        for (int i = 0; i < 8; ++i) {
            pv[i] += __shfl_xor_sync(0xffffffffu, pv[i], off);
            pd[i] += __shfl_xor_sync(0xffffffffu, pd[i], off);
        }
    }
    __syncthreads();
    float* stV = (float*)Bp;
    float* stD = stV + 512;
    if (tIG == 0) {
#pragma unroll
        for (int mi = 0; mi < 4; ++mi)
#pragma unroll
            for (int rh = 0; rh < 2; ++rh) {
                int row = wm + mi * 16 + rh * 8 + gID;
                stV[(wid & 3) * 128 + row] = pv[mi * 2 + rh];
                stD[(wid & 3) * 128 + row] = pd[mi * 2 + rh];
            }
    }
    __syncthreads();
    if (tid < 128) {
        float v = stV[tid] + stV[128 + tid] + stV[256 + tid] + stV[384 + tid];
        float d = stD[tid] + stD[128 + tid] + stD[256 + tid] + stD[384 + tid];
        int mm = mB + tid;
        out[mm] = v + vb[0];
        float s = d + db[0];
        out[MROWS + mm] = 1.f / (1.f + expf(-s)) * 0.4f + 0.1f;
    }
    GDC_LAUNCH();
}

// ---------------- launch -----------------------------------------------------
extern "C" void kernel_launch(void* const* d_in, const int* in_sizes, int n_in,
                              void* d_out, int out_size)
{
    (void)in_sizes; (void)n_in; (void)out_size;
    const float* obs  = (const float*)d_in[0];
    const float* sw1  = (const float*)d_in[1];
    const float* sb1  = (const float*)d_in[2];
    const float* sw2  = (const float*)d_in[3];
    const float* sb2  = (const float*)d_in[4];
    const float* uw1  = (const float*)d_in[5];
    const float* ub1  = (const float*)d_in[6];
    const float* uw2  = (const float*)d_in[7];
    const float* ub2  = (const float*)d_in[8];
    const float* noop = (const float*)d_in[9];
    const float* tw1  = (const float*)d_in[10];
    const float* tb1  = (const float*)d_in[11];
    const float* tw2  = (const float*)d_in[12];
    const float* tb2  = (const float*)d_in[13];
    const float* vw   = (const float*)d_in[14];
    const float* vb   = (const float*)d_in[15];
    const float* dw   = (const float*)d_in[16];
    const float* db   = (const float*)d_in[17];
    float* out = (float*)d_out;

    const int smemG = 6 * 128 * 40 * 2;              // 61440
    const int smemU = 8 * 128 * 40 * 2;              // 81920
    const int smemM = (16 * 5120 + 3 * 10240) * 2;   // 225280
    static bool attr_done = false;
    if (!attr_done) {
        cudaFuncSetAttribute(sec_gemm,   cudaFuncAttributeMaxDynamicSharedMemorySize, smemG);
        cudaFuncSetAttribute(ue_fused,   cudaFuncAttributeMaxDynamicSharedMemorySize, smemU);
        cudaFuncSetAttribute(mega_trunk, cudaFuncAttributeMaxDynamicSharedMemorySize, smemM);
        attr_done = true;
    }

    cudaLaunchAttribute at[1];
    at[0].id = cudaLaunchAttributeProgrammaticStreamSerialization;
    at[0].val.programmaticStreamSerializationAllowed = 1;

    auto mkcfg = [&](dim3 g, dim3 b, int smem) {
        cudaLaunchConfig_t c = {};
        c.gridDim = g; c.blockDim = b; c.dynamicSmemBytes = (size_t)smem;
        c.stream = 0; c.attrs = at; c.numAttrs = 1;
        return c;
    };

    {
        cudaLaunchConfig_t c = mkcfg(dim3(768), dim3(256), 0);
        cudaLaunchKernelEx(&c, prep_kernel, sw1, sw2, uw1, uw2, tw1, tw2);
    }
    {
        cudaLaunchConfig_t c = mkcfg(dim3(BB / 32), dim3(256), 0);
        cudaLaunchKernelEx(&c, se_kernel, obs, sb1, sb2);
    }
    {
        cudaLaunchConfig_t c = mkcfg(dim3(4, BB / 128), dim3(128), smemG);
        cudaLaunchKernelEx(&c, sec_gemm);
    }
    {
        cudaLaunchConfig_t c = mkcfg(dim3(MROWS / 128), dim3(128), smemU);
        cudaLaunchKernelEx(&c, ue_fused, obs, ub1, ub2, noop);
    }
    {
        cudaLaunchConfig_t c = mkcfg(dim3(MROWS / 128), dim3(256), smemM);
        cudaLaunchKernelEx(&c, mega_trunk, tb1, tb2, vw, dw, vb, db, out);
    }
}